// round 10
// baseline (speedup 1.0000x reference)
#include <cuda_runtime.h>

#define BDIM 2048
#define TDIM 128
#define FDIM 8
#define UO   128
#define UI   64
#define BT   16          // batch rows per CTA (two independent halves of 8)
#define HR   8           // rows per half
#define NTHR 256
#define BN_EPS 1e-3f

// ---------------- device scratch: BN-folded, gate-contiguous weights ---------
__device__ __align__(16) float g_Wk1t[FDIM * UO * 4];
__device__ __align__(16) float g_Wr1t[UO * UO * 4];
__device__ __align__(16) float g_Wr2t[UI * UI * 4];
__device__ __align__(16) float g_Wr3t[UI * UI * 4];
__device__ __align__(16) float g_Wr4t[UO * UO * 4];
__device__ __align__(16) float g_Wk2f[UO * UI * 4];   // BN1 folded
__device__ __align__(16) float g_Wk3f[UI * UI * 4];   // BN2 folded
__device__ __align__(16) float g_Wk4f[UI * UO * 4];   // BN3 folded
__device__ __align__(16) float g_Wdf[UO * FDIM];      // BN4 folded
__device__ float g_b2f[4 * UI];
__device__ float g_b3f[4 * UI];
__device__ float g_b4f[4 * UO];
__device__ float g_bdf[FDIM];

// ---------------- dynamic smem layout (floats) --------------------------------
#define SM_WBIG   0                            // 32768: Wk2f (A) / Wk4f (B)
#define SM_WSMALL 32768                        // 16384: Wr2t (A) / Wr3t (B)
#define SM_H1     (SM_WSMALL + 16384)          // 2048
#define SM_H2     (SM_H1 + 2048)               // 1024
#define SM_H3     (SM_H2 + 1024)               // 1024
#define SM_H4     (SM_H3 + 1024)               // 2048
#define SM_XS     (SM_H4 + 2048)               // 128
#define SM_WDS    (SM_XS + 128)                // 1024
#define SM_BDS    (SM_WDS + 1024)              // 8
#define SM_TOTAL  (SM_BDS + 8)                 // 56456 floats = 225824 B
#define SMEM_BYTES (SM_TOTAL * 4)

// ---------------- helpers ----------------------------------------------------
__device__ __forceinline__ float2 ffma2f(float2 a, float2 b, float2 c) {
    union U { float2 f; unsigned long long u; };
    U A, B, C, D;
    A.f = a; B.f = b; C.f = c;
    asm("fma.rn.f32x2 %0, %1, %2, %3;" : "=l"(D.u) : "l"(A.u), "l"(B.u), "l"(C.u));
    return D.f;
}

__device__ __forceinline__ void barsync(int id) {
    asm volatile("bar.sync %0, 128;" :: "r"(id) : "memory");
}

__device__ __forceinline__ float tanh_fast(float x) {
    float y;
    asm("tanh.approx.f32 %0, %1;" : "=f"(y) : "f"(x));
    return y;
}

// sigmoid(x) = 0.5*tanh(0.5x)+0.5 : 1 MUFU instead of 2
__device__ __forceinline__ float sigm(float x) {
    return fmaf(0.5f, tanh_fast(0.5f * x), 0.5f);
}

__device__ __forceinline__ float seluf(float x) {
    const float l = 1.0507009873554805f;
    const float a = 1.6732632423543772f;
    return x > 0.0f ? l * x : l * a * (__expf(x) - 1.0f);
}

__device__ __forceinline__ void gate_update(float zi, float zf, float zg, float zo,
                                            float& c, float& h) {
    float i = sigm(zi), f = sigm(zf), g = seluf(zg), o = sigm(zo);
    c = f * c + i * g;
    h = o * seluf(c);
}

// acc[4][4] covers 8 rows (2 quads); 16 FFMA2
__device__ __forceinline__ void acc8(float2 (&acc)[4][4], float4 w, float4 h0, float4 h1) {
    float ws[4] = {w.x, w.y, w.z, w.w};
#pragma unroll
    for (int g = 0; g < 4; g++) {
        float2 W = make_float2(ws[g], ws[g]);
        acc[g][0] = ffma2f(make_float2(h0.x, h0.y), W, acc[g][0]);
        acc[g][1] = ffma2f(make_float2(h0.z, h0.w), W, acc[g][1]);
        acc[g][2] = ffma2f(make_float2(h1.x, h1.y), W, acc[g][2]);
        acc[g][3] = ffma2f(make_float2(h1.z, h1.w), W, acc[g][3]);
    }
}

// acc[4][2] covers 4 rows (1 quad); 8 FFMA2
__device__ __forceinline__ void acc4(float2 (&acc)[4][2], float4 w, float4 h) {
    float ws[4] = {w.x, w.y, w.z, w.w};
#pragma unroll
    for (int g = 0; g < 4; g++) {
        float2 W = make_float2(ws[g], ws[g]);
        acc[g][0] = ffma2f(make_float2(h.x, h.y), W, acc[g][0]);
        acc[g][1] = ffma2f(make_float2(h.z, h.w), W, acc[g][1]);
    }
}

template <int NP>
__device__ __forceinline__ void init_acc(float2 (&acc)[4][NP], const float b[4]) {
#pragma unroll
    for (int g = 0; g < 4; g++)
#pragma unroll
        for (int p = 0; p < NP; p++) acc[g][p] = make_float2(b[g], b[g]);
}

// register-only gate math (no smem traffic) — safe to run BEFORE the barrier
template <int NP>
__device__ __forceinline__ void gates_compute(float2 (&acc)[4][NP], float* cvec, float* hout) {
#pragma unroll
    for (int p = 0; p < NP; p++) {
        {
            float c = cvec[2 * p], h;
            gate_update(acc[0][p].x, acc[1][p].x, acc[2][p].x, acc[3][p].x, c, h);
            cvec[2 * p] = c; hout[2 * p] = h;
        }
        {
            float c = cvec[2 * p + 1], h;
            gate_update(acc[0][p].y, acc[1][p].y, acc[2][p].y, acc[3][p].y, c, h);
            cvec[2 * p + 1] = c; hout[2 * p + 1] = h;
        }
    }
}

template <int NP>
__device__ __forceinline__ void gates_write(float2 (&acc)[4][NP], float* cvec, float* hrow) {
#pragma unroll
    for (int p = 0; p < NP; p++) {
        {
            float c = cvec[2 * p], h;
            gate_update(acc[0][p].x, acc[1][p].x, acc[2][p].x, acc[3][p].x, c, h);
            cvec[2 * p] = c; hrow[2 * p] = h;
        }
        {
            float c = cvec[2 * p + 1], h;
            gate_update(acc[0][p].y, acc[1][p].y, acc[2][p].y, acc[3][p].y, c, h);
            cvec[2 * p + 1] = c; hrow[2 * p + 1] = h;
        }
    }
}

// ---------------- single merged prep kernel -----------------------------------
#define N_WK1T  (FDIM * UO * 4)
#define N_WR1T  (UO * UO * 4)
#define N_WR2T  (UI * UI * 4)
#define N_WR3T  (UI * UI * 4)
#define N_WR4T  (UO * UO * 4)
#define N_WK2F  (UO * UI * 4)
#define N_WK3F  (UI * UI * 4)
#define N_WK4F  (UI * UO * 4)
#define N_WDF   (UO * FDIM)
#define O1 N_WK1T
#define O2 (O1 + N_WR1T)
#define O3 (O2 + N_WR2T)
#define O4 (O3 + N_WR3T)
#define O5 (O4 + N_WR4T)
#define O6 (O5 + N_WK2F)
#define O7 (O6 + N_WK3F)
#define O8 (O7 + N_WK4F)
#define O9 (O8 + N_WDF)
#define OA (O9 + 4 * UI)
#define OB (OA + 4 * UI)
#define OC (OB + 4 * UO)
#define OD (OC + FDIM)
#define NTOT OD

__device__ __forceinline__ float bn_s(const float* g, const float* v, int k) {
    return g[k] * rsqrtf(v[k] + BN_EPS);
}
__device__ __forceinline__ float bn_sh(const float* g, const float* be, const float* m,
                                       const float* v, int k) {
    float s = g[k] * rsqrtf(v[k] + BN_EPS);
    return be[k] - m[k] * s;
}

__global__ void prep_all(const float* __restrict__ Wk1, const float* __restrict__ Wr1,
                         const float* __restrict__ Wr2, const float* __restrict__ Wr3,
                         const float* __restrict__ Wr4,
                         const float* __restrict__ Wk2, const float* __restrict__ b2,
                         const float* __restrict__ Wk3, const float* __restrict__ b3,
                         const float* __restrict__ Wk4, const float* __restrict__ b4,
                         const float* __restrict__ Wd,  const float* __restrict__ bd,
                         const float* __restrict__ g1, const float* __restrict__ be1,
                         const float* __restrict__ m1, const float* __restrict__ v1,
                         const float* __restrict__ g2, const float* __restrict__ be2,
                         const float* __restrict__ m2, const float* __restrict__ v2,
                         const float* __restrict__ g3, const float* __restrict__ be3,
                         const float* __restrict__ m3, const float* __restrict__ v3,
                         const float* __restrict__ g4, const float* __restrict__ be4,
                         const float* __restrict__ m4, const float* __restrict__ v4) {
    int e = blockIdx.x * blockDim.x + threadIdx.x;
    if (e >= NTOT) return;
    if (e < O1) {
        int g = e & 3, u = (e >> 2) & (UO - 1), k = e >> 9;
        g_Wk1t[e] = Wk1[k * 4 * UO + g * UO + u];
    } else if (e < O2) {
        int i = e - O1;
        int g = i & 3, u = (i >> 2) & (UO - 1), k = i >> 9;
        g_Wr1t[i] = Wr1[k * 4 * UO + g * UO + u];
    } else if (e < O3) {
        int i = e - O2;
        int g = i & 3, u = (i >> 2) & (UI - 1), k = i >> 8;
        g_Wr2t[i] = Wr2[k * 4 * UI + g * UI + u];
    } else if (e < O4) {
        int i = e - O3;
        int g = i & 3, u = (i >> 2) & (UI - 1), k = i >> 8;
        g_Wr3t[i] = Wr3[k * 4 * UI + g * UI + u];
    } else if (e < O5) {
        int i = e - O4;
        int g = i & 3, u = (i >> 2) & (UO - 1), k = i >> 9;
        g_Wr4t[i] = Wr4[k * 4 * UO + g * UO + u];
    } else if (e < O6) {
        int i = e - O5;
        int g = i & 3, u = (i >> 2) & (UI - 1), k = i >> 8;
        g_Wk2f[i] = bn_s(g1, v1, k) * Wk2[k * 4 * UI + g * UI + u];
    } else if (e < O7) {
        int i = e - O6;
        int g = i & 3, u = (i >> 2) & (UI - 1), k = i >> 8;
        g_Wk3f[i] = bn_s(g2, v2, k) * Wk3[k * 4 * UI + g * UI + u];
    } else if (e < O8) {
        int i = e - O7;
        int g = i & 3, u = (i >> 2) & (UO - 1), k = i >> 9;
        g_Wk4f[i] = bn_s(g3, v3, k) * Wk4[k * 4 * UO + g * UO + u];
    } else if (e < O9) {
        int i = e - O8;
        int k = i >> 3;
        g_Wdf[i] = bn_s(g4, v4, k) * Wd[i];
    } else if (e < OA) {
        int c = e - O9;
        float acc = b2[c];
        for (int k = 0; k < UO; k++) acc += bn_sh(g1, be1, m1, v1, k) * Wk2[k * 4 * UI + c];
        g_b2f[c] = acc;
    } else if (e < OB) {
        int c = e - OA;
        float acc = b3[c];
        for (int k = 0; k < UI; k++) acc += bn_sh(g2, be2, m2, v2, k) * Wk3[k * 4 * UI + c];
        g_b3f[c] = acc;
    } else if (e < OC) {
        int c = e - OB;
        float acc = b4[c];
        for (int k = 0; k < UI; k++) acc += bn_sh(g3, be3, m3, v3, k) * Wk4[k * 4 * UO + c];
        g_b4f[c] = acc;
    } else {
        int c = e - OC;
        float acc = bd[c];
        for (int k = 0; k < UO; k++) acc += bn_sh(g4, be4, m4, v4, k) * Wd[k * FDIM + c];
        g_bdf[c] = acc;
    }
}

// 8-deep weight-block load into register buffer
#define LD8(BUF, BASE, K0)                                                  \
    do {                                                                    \
        _Pragma("unroll")                                                   \
        for (int j_ = 0; j_ < 8; j_++)                                      \
            BUF[j_] = __ldg((BASE) + ((K0) + j_) * UO + ub);                \
    } while (0)

// phase A block bodies
#define BODYA_WR(K0, BUF)                                                   \
    do {                                                                    \
        _Pragma("unroll")                                                   \
        for (int j_ = 0; j_ < 8; j_++) {                                    \
            int k_ = (K0) + j_;                                             \
            float4 w2_ = wbig4[k_ * UI + us];                               \
            float4 wr_ = wsmall4[k_ * UI + us];                             \
            const float4* hq_ = (const float4*)(h1 + k_ * HR);              \
            float4 h1a_ = hq_[0], h1b_ = hq_[1];                            \
            float4 h1sel_ = hiq ? h1b_ : h1a_;                              \
            float4 h2q_ = *(const float4*)(h2 + k_ * HR + rs);              \
            acc8(a1, BUF[j_], h1a_, h1b_);                                  \
            acc4(a2, w2_, h1sel_);                                          \
            acc4(a2, wr_, h2q_);                                            \
        }                                                                   \
    } while (0)

#define BODYA_NW(K0, BUF)                                                   \
    do {                                                                    \
        _Pragma("unroll")                                                   \
        for (int j_ = 0; j_ < 8; j_++) {                                    \
            int k_ = (K0) + j_;                                             \
            float4 w2_ = wbig4[k_ * UI + us];                               \
            const float4* hq_ = (const float4*)(h1 + k_ * HR);              \
            float4 h1a_ = hq_[0], h1b_ = hq_[1];                            \
            float4 h1sel_ = hiq ? h1b_ : h1a_;                              \
            acc8(a1, BUF[j_], h1a_, h1b_);                                  \
            acc4(a2, w2_, h1sel_);                                          \
        }                                                                   \
    } while (0)

// phase B block bodies
#define BODYB_WR(K0, BUF)                                                   \
    do {                                                                    \
        _Pragma("unroll")                                                   \
        for (int j_ = 0; j_ < 8; j_++) {                                    \
            int k_ = (K0) + j_;                                             \
            float4 wk_ = wbig4[k_ * UO + ub];                               \
            float4 w3_ = wsmall4[k_ * UI + us];                             \
            const float4* h4q_ = (const float4*)(h4 + k_ * HR);             \
            float4 h4a_ = h4q_[0], h4b_ = h4q_[1];                          \
            const float4* h3q_ = (const float4*)(h3 + k_ * HR);             \
            float4 h3a_ = h3q_[0], h3b_ = h3q_[1];                          \
            float4 h3sel_ = hiq ? h3b_ : h3a_;                              \
            acc8(a4, BUF[j_], h4a_, h4b_);                                  \
            acc8(a4, wk_, h3a_, h3b_);                                      \
            acc4(a3, w3_, h3sel_);                                          \
        }                                                                   \
    } while (0)

#define BODYB_NW(K0, BUF)                                                   \
    do {                                                                    \
        _Pragma("unroll")                                                   \
        for (int j_ = 0; j_ < 8; j_++) {                                    \
            const float4* h4q_ = (const float4*)(h4 + ((K0) + j_) * HR);    \
            acc8(a4, BUF[j_], h4q_[0], h4q_[1]);                            \
        }                                                                   \
    } while (0)

// ---------------- main: ping-pong LDG pipeline + pre-barrier gate math --------
__global__ __launch_bounds__(NTHR, 1)
void lstm_ae_kernel(const float* __restrict__ x,
                    const float* __restrict__ b1,
                    float* __restrict__ out) {
    extern __shared__ __align__(16) float sm[];
    float* wbig   = sm + SM_WBIG;     // Wk2f (phase A) / Wk4f (phase B)
    float* wsmall = sm + SM_WSMALL;   // Wr2t (phase A) / Wr3t (phase B)
    float* wds    = sm + SM_WDS;
    float* bds    = sm + SM_BDS;

    const int tid  = threadIdx.x;
    const int half = tid >> 7;
    const int ltid = tid & 127;
    const int bid  = 1 + half;
    const int row0 = blockIdx.x * BT + half * HR;

    float* h1 = sm + SM_H1 + half * (UO * HR);
    float* h2 = sm + SM_H2 + half * (UI * HR);
    float* h3 = sm + SM_H3 + half * (UI * HR);
    float* h4 = sm + SM_H4 + half * (UO * HR);
    float* xh = sm + SM_XS + half * (FDIM * HR);

    const int ub = ltid;                 // big GEMMs: u-quad, all 8 rows
    const int us = ltid & 63;            // small GEMMs: u-quad
    const int rs = (ltid >> 6) * 4;      // small GEMMs: row-quad offset (0 or 4)
    const bool hiq = (ltid >= 64);       // warp-uniform: which quad rs selects

    // zero state, load dense weights, stage phase-A smem weights
    for (int i = tid; i < UO * HR * 2; i += NTHR) { sm[SM_H1 + i] = 0.f; sm[SM_H4 + i] = 0.f; }
    for (int i = tid; i < UI * HR * 2; i += NTHR) { sm[SM_H2 + i] = 0.f; sm[SM_H3 + i] = 0.f; }
    for (int i = tid; i < UO * FDIM; i += NTHR) wds[i] = g_Wdf[i];
    if (tid < FDIM) bds[tid] = g_bdf[tid];
    if (ltid < HR * FDIM) {
        int r = ltid >> 3, k = ltid & 7;
        xh[k * HR + r] = x[(size_t)(row0 + r) * TDIM * FDIM + k];
    }
    {
        float4* d1 = (float4*)wbig;
        const float4* s1 = (const float4*)g_Wk2f;
        for (int i = tid; i < N_WK2F / 4; i += NTHR) d1[i] = s1[i];
        float4* d2 = (float4*)wsmall;
        const float4* s2 = (const float4*)g_Wr2t;
        for (int i = tid; i < N_WR2T / 4; i += NTHR) d2[i] = s2[i];
    }

    float bb1[4], bb2[4], bb4[4];
#pragma unroll
    for (int g = 0; g < 4; g++) {
        bb1[g] = b1[g * UO + ub];
        bb2[g] = g_b2f[g * UI + us];
        bb4[g] = g_b4f[g * UO + ub];
    }

    float c1v[8], c4v[8], c2v[4], c3v[4];
#pragma unroll
    for (int i = 0; i < 8; i++) { c1v[i] = 0.f; c4v[i] = 0.f; }
#pragma unroll
    for (int i = 0; i < 4; i++) { c2v[i] = 0.f; c3v[i] = 0.f; }

    const float4* Wk1t = (const float4*)g_Wk1t;
    const float4* Wr1t = (const float4*)g_Wr1t;
    const float4* Wr4t = (const float4*)g_Wr4t;
    const float4* Wk3f = (const float4*)g_Wk3f;
    const float4* wbig4   = (const float4*)wbig;
    const float4* wsmall4 = (const float4*)wsmall;

    const int xr = ltid >> 3, xk = ltid & 7;

    __syncthreads();

    // ========== Phase A: LSTM1(t) fused with LSTM2(t-1), pipelined ==========
    // Loop-top invariant: h1 = h1(t-1), h2 = h2(t-2), xh = x(t).
    for (int t = 0; t < TDIM; t++) {
        float2 a1[4][4];
        init_acc<4>(a1, bb1);
        float2 a2[4][2];
        init_acc<2>(a2, bb2);

        float4 wA[8], wB[8];

        // stage x weights + block-0 of Wr1t, then consume x (covers block-0 latency)
        {
            float4 xw[FDIM];
#pragma unroll
            for (int k = 0; k < FDIM; k++) xw[k] = __ldg(Wk1t + k * UO + ub);
            LD8(wA, Wr1t, 0);
#pragma unroll
            for (int k = 0; k < FDIM; k++) {
                const float4* xq = (const float4*)(xh + k * HR);
                acc8(a1, xw[k], xq[0], xq[1]);
            }
        }
#pragma unroll 1
        for (int k0 = 0; k0 < 64; k0 += 16) {
            LD8(wB, Wr1t, k0 + 8);
            BODYA_WR(k0, wA);
            LD8(wA, Wr1t, k0 + 16);        // at k0=48 this preloads block 64
            BODYA_WR(k0 + 8, wB);
        }
#pragma unroll 1
        for (int k0 = 64; k0 < 128; k0 += 16) {
            LD8(wB, Wr1t, k0 + 8);
            BODYA_NW(k0, wA);
            LD8(wA, Wr1t, (k0 + 16) & 127);  // wrap keeps address valid
            BODYA_NW(k0 + 8, wB);
        }

        // ---- pre-barrier: gate math in registers + x(t+1) gmem load --------
        float h1n[8], h2n[4];
        gates_compute<4>(a1, c1v, h1n);                       // h1(t)
        if (t > 0) gates_compute<2>(a2, c2v, h2n);            // h2(t-1)
        float xnew = 0.f;
        const bool do_x = (t + 1 < TDIM) && (ltid < HR * FDIM);
        if (do_x) xnew = __ldg(x + (size_t)(row0 + xr) * TDIM * FDIM + (t + 1) * FDIM + xk);

        barsync(bid);  // old-state reads complete

        // ---- post-barrier: stores only ------------------------------------
        *(float4*)(h1 + ub * HR)     = make_float4(h1n[0], h1n[1], h1n[2], h1n[3]);
        *(float4*)(h1 + ub * HR + 4) = make_float4(h1n[4], h1n[5], h1n[6], h1n[7]);
        if (t > 0)
            *(float4*)(h2 + us * HR + rs) = make_float4(h2n[0], h2n[1], h2n[2], h2n[3]);
        if (do_x) xh[xk * HR + xr] = xnew;
        barsync(bid);  // new state visible
    }

    // epilogue A: h2(127) from h1(127), h2(126)
    {
        float2 a2[4][2];
        init_acc<2>(a2, bb2);
#pragma unroll 4
        for (int k = 0; k < UI; k++) {
            float4 w2 = wbig4[k * UI + us];
            float4 wr = wsmall4[k * UI + us];
            float4 h1sel = *(const float4*)(h1 + k * HR + rs);
            float4 h2q  = *(const float4*)(h2 + k * HR + rs);
            acc4(a2, w2, h1sel);
            acc4(a2, wr, h2q);
        }
#pragma unroll 4
        for (int k = UI; k < UO; k++) {
            float4 w2 = wbig4[k * UI + us];
            float4 h1sel = *(const float4*)(h1 + k * HR + rs);
            acc4(a2, w2, h1sel);
        }
        barsync(bid);
        gates_write<2>(a2, c2v, h2 + us * HR + rs);  // h2(127)
    }

    // ===== transition: xz3 = enc_bn @ Wk3f + b3f; reload smem for phase B ====
    __syncthreads();   // join halves; h2 final everywhere
    float2 x3[4][2];
    {
        float bb3[4];
#pragma unroll
        for (int g = 0; g < 4; g++) bb3[g] = g_b3f[g * UI + us];
        init_acc<2>(x3, bb3);
#pragma unroll 4
        for (int k = 0; k < UI; k++) {
            float4 w = __ldg(Wk3f + k * UI + us);
            float4 hq = *(const float4*)(h2 + k * HR + rs);
            acc4(x3, w, hq);
        }
    }
    {
        float4* d1 = (float4*)wbig;
        const float4* s1 = (const float4*)g_Wk4f;
        for (int i = tid; i < N_WK4F / 4; i += NTHR) d1[i] = s1[i];
        float4* d2 = (float4*)wsmall;
        const float4* s2 = (const float4*)g_Wr3t;
        for (int i = tid; i < N_WR3T / 4; i += NTHR) d2[i] = s2[i];
    }
    __syncthreads();   // phase-B weights staged

    // ========== Phase B: LSTM3(t) fused with LSTM4(t-1) + Dense(t-2) ========
    // Loop-top invariant: h3 = h3(t-1), h4 = h4(t-2).
    const int dr = ltid >> 3, dc = ltid & 7;
    for (int t = 0; t < TDIM; t++) {
        float2 a3[4][2];
#pragma unroll
        for (int g = 0; g < 4; g++) { a3[g][0] = x3[g][0]; a3[g][1] = x3[g][1]; }
        float2 a4[4][4];
        init_acc<4>(a4, bb4);

        float4 wA[8], wB[8];
        LD8(wA, Wr4t, 0);

        // dense head out(t-2) from h4(t-2) — covers block-0 latency
        if (t >= 2 && ltid < HR * FDIM) {
            float acc = bds[dc];
#pragma unroll 8
            for (int k = 0; k < UO; k++) acc += h4[k * HR + dr] * wds[k * FDIM + dc];
            out[(size_t)(row0 + dr) * TDIM * FDIM + (t - 2) * FDIM + dc] = acc;
        }

#pragma unroll 1
        for (int k0 = 0; k0 < 64; k0 += 16) {
            LD8(wB, Wr4t, k0 + 8);
            BODYB_WR(k0, wA);
            LD8(wA, Wr4t, k0 + 16);        // at k0=48 preloads block 64
            BODYB_WR(k0 + 8, wB);
        }
#pragma unroll 1
        for (int k0 = 64; k0 < 128; k0 += 16) {
            LD8(wB, Wr4t, k0 + 8);
            BODYB_NW(k0, wA);
            LD8(wA, Wr4t, (k0 + 16) & 127);
            BODYB_NW(k0 + 8, wB);
        }

        // ---- pre-barrier: gate math in registers ---------------------------
        float h3n[4], h4n[8];
        gates_compute<2>(a3, c3v, h3n);                       // h3(t)
        if (t > 0) gates_compute<4>(a4, c4v, h4n);            // h4(t-1)

        barsync(bid);  // old-state reads complete

        // ---- post-barrier: stores only ------------------------------------
        *(float4*)(h3 + us * HR + rs) = make_float4(h3n[0], h3n[1], h3n[2], h3n[3]);
        if (t > 0) {
            *(float4*)(h4 + ub * HR)     = make_float4(h4n[0], h4n[1], h4n[2], h4n[3]);
            *(float4*)(h4 + ub * HR + 4) = make_float4(h4n[4], h4n[5], h4n[6], h4n[7]);
        }
        barsync(bid);  // new state visible
    }

    // epilogue B: h4(127) from h4(126), h3(127); dense out(126), out(127)
    {
        float2 a4[4][4];
        init_acc<4>(a4, bb4);
#pragma unroll 4
        for (int k = 0; k < UI; k++) {
            float4 w4 = __ldg(Wr4t + k * UO + ub);
            float4 wk = wbig4[k * UO + ub];
            const float4* h4q = (const float4*)(h4 + k * HR);
            const float4* h3q = (const float4*)(h3 + k * HR);
            acc8(a4, w4, h4q[0], h4q[1]);
            acc8(a4, wk, h3q[0], h3q[1]);
        }
#pragma unroll 4
        for (int k = UI; k < UO; k++) {
            float4 w4 = __ldg(Wr4t + k * UO + ub);
            const float4* h4q = (const float4*)(h4 + k * HR);
            acc8(a4, w4, h4q[0], h4q[1]);
        }
        if (ltid < HR * FDIM) {  // out(126) from h4(126)
            float acc = bds[dc];
#pragma unroll 8
            for (int k = 0; k < UO; k++) acc += h4[k * HR + dr] * wds[k * FDIM + dc];
            out[(size_t)(row0 + dr) * TDIM * FDIM + 126 * FDIM + dc] = acc;
        }
        barsync(bid);
        gates_write<4>(a4, c4v, h4 + ub * HR);  // h4(127)
        barsync(bid);
        if (ltid < HR * FDIM) {  // out(127)
            float acc = bds[dc];
#pragma unroll 8
            for (int k = 0; k < UO; k++) acc += h4[k * HR + dr] * wds[k * FDIM + dc];
            out[(size_t)(row0 + dr) * TDIM * FDIM + 127 * FDIM + dc] = acc;
        }
    }
}

// ---------------- launch ------------------------------------------------------
extern "C" void kernel_launch(void* const* d_in, const int* in_sizes, int n_in,
                              void* d_out, int out_size) {
    const float* x   = (const float*)d_in[0];
    const float* Wk1 = (const float*)d_in[1];
    const float* Wr1 = (const float*)d_in[2];
    const float* b1  = (const float*)d_in[3];
    const float* g1  = (const float*)d_in[4];
    const float* be1 = (const float*)d_in[5];
    const float* m1  = (const float*)d_in[6];
    const float* v1  = (const float*)d_in[7];
    const float* Wk2 = (const float*)d_in[8];
    const float* Wr2 = (const float*)d_in[9];
    const float* b2  = (const float*)d_in[10];
    const float* g2  = (const float*)d_in[11];
    const float* be2 = (const float*)d_in[12];
    const float* m2  = (const float*)d_in[13];
    const float* v2  = (const float*)d_in[14];
    const float* Wk3 = (const float*)d_in[15];
    const float* Wr3 = (const float*)d_in[16];
    const float* b3  = (const float*)d_in[17];
    const float* g3  = (const float*)d_in[18];
    const float* be3 = (const float*)d_in[19];
    const float* m3  = (const float*)d_in[20];
    const float* v3  = (const float*)d_in[21];
    const float* Wk4 = (const float*)d_in[22];
    const float* Wr4 = (const float*)d_in[23];
    const float* b4  = (const float*)d_in[24];
    const float* g4  = (const float*)d_in[25];
    const float* be4 = (const float*)d_in[26];
    const float* m4  = (const float*)d_in[27];
    const float* v4  = (const float*)d_in[28];
    const float* Wd  = (const float*)d_in[29];
    const float* bd  = (const float*)d_in[30];

    static bool attr_set = false;
    if (!attr_set) {
        cudaFuncSetAttribute(lstm_ae_kernel,
                             cudaFuncAttributeMaxDynamicSharedMemorySize, SMEM_BYTES);
        attr_set = true;
    }

    prep_all<<<(NTOT + 255) / 256, 256>>>(Wk1, Wr1, Wr2, Wr3, Wr4,
                                          Wk2, b2, Wk3, b3, Wk4, b4, Wd, bd,
                                          g1, be1, m1, v1, g2, be2, m2, v2,
                                          g3, be3, m3, v3, g4, be4, m4, v4);
    lstm_ae_kernel<<<BDIM / BT, NTHR, SMEM_BYTES>>>(x, b1, (float*)d_out);
}

// round 11
// speedup vs baseline: 1.1066x; 1.1066x over previous
#include <cuda_runtime.h>

#define BDIM 2048
#define TDIM 128
#define FDIM 8
#define UO   128
#define UI   64
#define BT   16          // batch rows per CTA (two independent halves of 8)
#define HR   8           // rows per half
#define NTHR 256
#define BN_EPS 1e-3f

// ---------------- device scratch: BN-folded, gate-contiguous weights ---------
__device__ __align__(16) float g_Wk1t[FDIM * UO * 4];
__device__ __align__(16) float g_Wr1t[UO * UO * 4];
__device__ __align__(16) float g_Wr2t[UI * UI * 4];
__device__ __align__(16) float g_Wr3t[UI * UI * 4];
__device__ __align__(16) float g_Wr4t[UO * UO * 4];
__device__ __align__(16) float g_Wk2f[UO * UI * 4];   // BN1 folded
__device__ __align__(16) float g_Wk3f[UI * UI * 4];   // BN2 folded
__device__ __align__(16) float g_Wk4f[UI * UO * 4];   // BN3 folded
__device__ __align__(16) float g_Wdf[UO * FDIM];      // BN4 folded
__device__ float g_b2f[4 * UI];
__device__ float g_b3f[4 * UI];
__device__ float g_b4f[4 * UO];
__device__ float g_bdf[FDIM];

// ---------------- dynamic smem layout (floats) --------------------------------
#define SM_WBIG   0                            // 32768: Wk2f (A) / Wk4f (B)
#define SM_WSMALL 32768                        // 16384: Wr2t (A) / Wr3t (B)
#define SM_H1     (SM_WSMALL + 16384)          // 2048
#define SM_H2     (SM_H1 + 2048)               // 1024
#define SM_H3     (SM_H2 + 1024)               // 1024
#define SM_H4     (SM_H3 + 1024)               // 2048
#define SM_XS     (SM_H4 + 2048)               // 128
#define SM_WDS    (SM_XS + 128)                // 1024
#define SM_BDS    (SM_WDS + 1024)              // 8
#define SM_TOTAL  (SM_BDS + 8)                 // 56456 floats = 225824 B
#define SMEM_BYTES (SM_TOTAL * 4)

// ---------------- helpers ----------------------------------------------------
__device__ __forceinline__ float2 ffma2f(float2 a, float2 b, float2 c) {
    union U { float2 f; unsigned long long u; };
    U A, B, C, D;
    A.f = a; B.f = b; C.f = c;
    asm("fma.rn.f32x2 %0, %1, %2, %3;" : "=l"(D.u) : "l"(A.u), "l"(B.u), "l"(C.u));
    return D.f;
}

__device__ __forceinline__ void barsync(int id) {
    asm volatile("bar.sync %0, 128;" :: "r"(id) : "memory");
}

__device__ __forceinline__ float tanh_fast(float x) {
    float y;
    asm("tanh.approx.f32 %0, %1;" : "=f"(y) : "f"(x));
    return y;
}

// sigmoid(x) = 0.5*tanh(0.5x)+0.5 : 1 MUFU instead of 2
__device__ __forceinline__ float sigm(float x) {
    return fmaf(0.5f, tanh_fast(0.5f * x), 0.5f);
}

__device__ __forceinline__ float seluf(float x) {
    const float l = 1.0507009873554805f;
    const float a = 1.6732632423543772f;
    return x > 0.0f ? l * x : l * a * (__expf(x) - 1.0f);
}

__device__ __forceinline__ void gate_update(float zi, float zf, float zg, float zo,
                                            float& c, float& h) {
    float i = sigm(zi), f = sigm(zf), g = seluf(zg), o = sigm(zo);
    c = f * c + i * g;
    h = o * seluf(c);
}

// acc[4][4] covers 8 rows (2 quads); 16 FFMA2
__device__ __forceinline__ void acc8(float2 (&acc)[4][4], float4 w, float4 h0, float4 h1) {
    float ws[4] = {w.x, w.y, w.z, w.w};
#pragma unroll
    for (int g = 0; g < 4; g++) {
        float2 W = make_float2(ws[g], ws[g]);
        acc[g][0] = ffma2f(make_float2(h0.x, h0.y), W, acc[g][0]);
        acc[g][1] = ffma2f(make_float2(h0.z, h0.w), W, acc[g][1]);
        acc[g][2] = ffma2f(make_float2(h1.x, h1.y), W, acc[g][2]);
        acc[g][3] = ffma2f(make_float2(h1.z, h1.w), W, acc[g][3]);
    }
}

// acc[4][2] covers 4 rows (1 quad); 8 FFMA2
__device__ __forceinline__ void acc4(float2 (&acc)[4][2], float4 w, float4 h) {
    float ws[4] = {w.x, w.y, w.z, w.w};
#pragma unroll
    for (int g = 0; g < 4; g++) {
        float2 W = make_float2(ws[g], ws[g]);
        acc[g][0] = ffma2f(make_float2(h.x, h.y), W, acc[g][0]);
        acc[g][1] = ffma2f(make_float2(h.z, h.w), W, acc[g][1]);
    }
}

template <int NP>
__device__ __forceinline__ void init_acc(float2 (&acc)[4][NP], const float b[4]) {
#pragma unroll
    for (int g = 0; g < 4; g++)
#pragma unroll
        for (int p = 0; p < NP; p++) acc[g][p] = make_float2(b[g], b[g]);
}

template <int NP>
__device__ __forceinline__ void gates_write(float2 (&acc)[4][NP], float* cvec, float* hrow) {
#pragma unroll
    for (int p = 0; p < NP; p++) {
        {
            float c = cvec[2 * p], h;
            gate_update(acc[0][p].x, acc[1][p].x, acc[2][p].x, acc[3][p].x, c, h);
            cvec[2 * p] = c; hrow[2 * p] = h;
        }
        {
            float c = cvec[2 * p + 1], h;
            gate_update(acc[0][p].y, acc[1][p].y, acc[2][p].y, acc[3][p].y, c, h);
            cvec[2 * p + 1] = c; hrow[2 * p + 1] = h;
        }
    }
}

// ---------------- single merged prep kernel -----------------------------------
#define N_WK1T  (FDIM * UO * 4)
#define N_WR1T  (UO * UO * 4)
#define N_WR2T  (UI * UI * 4)
#define N_WR3T  (UI * UI * 4)
#define N_WR4T  (UO * UO * 4)
#define N_WK2F  (UO * UI * 4)
#define N_WK3F  (UI * UI * 4)
#define N_WK4F  (UI * UO * 4)
#define N_WDF   (UO * FDIM)
#define O1 N_WK1T
#define O2 (O1 + N_WR1T)
#define O3 (O2 + N_WR2T)
#define O4 (O3 + N_WR3T)
#define O5 (O4 + N_WR4T)
#define O6 (O5 + N_WK2F)
#define O7 (O6 + N_WK3F)
#define O8 (O7 + N_WK4F)
#define O9 (O8 + N_WDF)
#define OA (O9 + 4 * UI)
#define OB (OA + 4 * UI)
#define OC (OB + 4 * UO)
#define OD (OC + FDIM)
#define NTOT OD

__device__ __forceinline__ float bn_s(const float* g, const float* v, int k) {
    return g[k] * rsqrtf(v[k] + BN_EPS);
}
__device__ __forceinline__ float bn_sh(const float* g, const float* be, const float* m,
                                       const float* v, int k) {
    float s = g[k] * rsqrtf(v[k] + BN_EPS);
    return be[k] - m[k] * s;
}

__global__ void prep_all(const float* __restrict__ Wk1, const float* __restrict__ Wr1,
                         const float* __restrict__ Wr2, const float* __restrict__ Wr3,
                         const float* __restrict__ Wr4,
                         const float* __restrict__ Wk2, const float* __restrict__ b2,
                         const float* __restrict__ Wk3, const float* __restrict__ b3,
                         const float* __restrict__ Wk4, const float* __restrict__ b4,
                         const float* __restrict__ Wd,  const float* __restrict__ bd,
                         const float* __restrict__ g1, const float* __restrict__ be1,
                         const float* __restrict__ m1, const float* __restrict__ v1,
                         const float* __restrict__ g2, const float* __restrict__ be2,
                         const float* __restrict__ m2, const float* __restrict__ v2,
                         const float* __restrict__ g3, const float* __restrict__ be3,
                         const float* __restrict__ m3, const float* __restrict__ v3,
                         const float* __restrict__ g4, const float* __restrict__ be4,
                         const float* __restrict__ m4, const float* __restrict__ v4) {
    int e = blockIdx.x * blockDim.x + threadIdx.x;
    if (e >= NTOT) return;
    if (e < O1) {
        int g = e & 3, u = (e >> 2) & (UO - 1), k = e >> 9;
        g_Wk1t[e] = Wk1[k * 4 * UO + g * UO + u];
    } else if (e < O2) {
        int i = e - O1;
        int g = i & 3, u = (i >> 2) & (UO - 1), k = i >> 9;
        g_Wr1t[i] = Wr1[k * 4 * UO + g * UO + u];
    } else if (e < O3) {
        int i = e - O2;
        int g = i & 3, u = (i >> 2) & (UI - 1), k = i >> 8;
        g_Wr2t[i] = Wr2[k * 4 * UI + g * UI + u];
    } else if (e < O4) {
        int i = e - O3;
        int g = i & 3, u = (i >> 2) & (UI - 1), k = i >> 8;
        g_Wr3t[i] = Wr3[k * 4 * UI + g * UI + u];
    } else if (e < O5) {
        int i = e - O4;
        int g = i & 3, u = (i >> 2) & (UO - 1), k = i >> 9;
        g_Wr4t[i] = Wr4[k * 4 * UO + g * UO + u];
    } else if (e < O6) {
        int i = e - O5;
        int g = i & 3, u = (i >> 2) & (UI - 1), k = i >> 8;
        g_Wk2f[i] = bn_s(g1, v1, k) * Wk2[k * 4 * UI + g * UI + u];
    } else if (e < O7) {
        int i = e - O6;
        int g = i & 3, u = (i >> 2) & (UI - 1), k = i >> 8;
        g_Wk3f[i] = bn_s(g2, v2, k) * Wk3[k * 4 * UI + g * UI + u];
    } else if (e < O8) {
        int i = e - O7;
        int g = i & 3, u = (i >> 2) & (UO - 1), k = i >> 9;
        g_Wk4f[i] = bn_s(g3, v3, k) * Wk4[k * 4 * UO + g * UO + u];
    } else if (e < O9) {
        int i = e - O8;
        int k = i >> 3;
        g_Wdf[i] = bn_s(g4, v4, k) * Wd[i];
    } else if (e < OA) {
        int c = e - O9;
        float acc = b2[c];
        for (int k = 0; k < UO; k++) acc += bn_sh(g1, be1, m1, v1, k) * Wk2[k * 4 * UI + c];
        g_b2f[c] = acc;
    } else if (e < OB) {
        int c = e - OA;
        float acc = b3[c];
        for (int k = 0; k < UI; k++) acc += bn_sh(g2, be2, m2, v2, k) * Wk3[k * 4 * UI + c];
        g_b3f[c] = acc;
    } else if (e < OC) {
        int c = e - OB;
        float acc = b4[c];
        for (int k = 0; k < UI; k++) acc += bn_sh(g3, be3, m3, v3, k) * Wk4[k * 4 * UO + c];
        g_b4f[c] = acc;
    } else {
        int c = e - OC;
        float acc = bd[c];
        for (int k = 0; k < UO; k++) acc += bn_sh(g4, be4, m4, v4, k) * Wd[k * FDIM + c];
        g_bdf[c] = acc;
    }
}

// 8-deep weight-block load into register buffer
#define LD8(BUF, BASE, K0)                                                  \
    do {                                                                    \
        _Pragma("unroll")                                                   \
        for (int j_ = 0; j_ < 8; j_++)                                      \
            BUF[j_] = __ldg((BASE) + ((K0) + j_) * UO + ub);                \
    } while (0)

// phase A block bodies
#define BODYA_WR(K0, BUF)                                                   \
    do {                                                                    \
        _Pragma("unroll")                                                   \
        for (int j_ = 0; j_ < 8; j_++) {                                    \
            int k_ = (K0) + j_;                                             \
            float4 w2_ = wbig4[k_ * UI + us];                               \
            float4 wr_ = wsmall4[k_ * UI + us];                             \
            const float4* hq_ = (const float4*)(h1 + k_ * HR);              \
            float4 h1a_ = hq_[0], h1b_ = hq_[1];                            \
            float4 h1sel_ = hiq ? h1b_ : h1a_;                              \
            float4 h2q_ = *(const float4*)(h2 + k_ * HR + rs);              \
            acc8(a1, BUF[j_], h1a_, h1b_);                                  \
            acc4(a2, w2_, h1sel_);                                          \
            acc4(a2, wr_, h2q_);                                            \
        }                                                                   \
    } while (0)

#define BODYA_NW(K0, BUF)                                                   \
    do {                                                                    \
        _Pragma("unroll")                                                   \
        for (int j_ = 0; j_ < 8; j_++) {                                    \
            int k_ = (K0) + j_;                                             \
            float4 w2_ = wbig4[k_ * UI + us];                               \
            const float4* hq_ = (const float4*)(h1 + k_ * HR);              \
            float4 h1a_ = hq_[0], h1b_ = hq_[1];                            \
            float4 h1sel_ = hiq ? h1b_ : h1a_;                              \
            acc8(a1, BUF[j_], h1a_, h1b_);                                  \
            acc4(a2, w2_, h1sel_);                                          \
        }                                                                   \
    } while (0)

// phase B block bodies
#define BODYB_WR(K0, BUF)                                                   \
    do {                                                                    \
        _Pragma("unroll")                                                   \
        for (int j_ = 0; j_ < 8; j_++) {                                    \
            int k_ = (K0) + j_;                                             \
            float4 wk_ = wbig4[k_ * UO + ub];                               \
            float4 w3_ = wsmall4[k_ * UI + us];                             \
            const float4* h4q_ = (const float4*)(h4 + k_ * HR);             \
            float4 h4a_ = h4q_[0], h4b_ = h4q_[1];                          \
            const float4* h3q_ = (const float4*)(h3 + k_ * HR);             \
            float4 h3a_ = h3q_[0], h3b_ = h3q_[1];                          \
            float4 h3sel_ = hiq ? h3b_ : h3a_;                              \
            acc8(a4, BUF[j_], h4a_, h4b_);                                  \
            acc8(a4, wk_, h3a_, h3b_);                                      \
            acc4(a3, w3_, h3sel_);                                          \
        }                                                                   \
    } while (0)

#define BODYB_NW(K0, BUF)                                                   \
    do {                                                                    \
        _Pragma("unroll")                                                   \
        for (int j_ = 0; j_ < 8; j_++) {                                    \
            const float4* h4q_ = (const float4*)(h4 + ((K0) + j_) * HR);    \
            acc8(a4, BUF[j_], h4q_[0], h4q_[1]);                            \
        }                                                                   \
    } while (0)

// ---------------- main: ping-pong LDG pipeline + pair-broadcast small GEMM ----
__global__ __launch_bounds__(NTHR, 1)
void lstm_ae_kernel(const float* __restrict__ x,
                    const float* __restrict__ b1,
                    float* __restrict__ out) {
    extern __shared__ __align__(16) float sm[];
    float* wbig   = sm + SM_WBIG;     // Wk2f (phase A) / Wk4f (phase B)
    float* wsmall = sm + SM_WSMALL;   // Wr2t (phase A) / Wr3t (phase B)
    float* wds    = sm + SM_WDS;
    float* bds    = sm + SM_BDS;

    const int tid  = threadIdx.x;
    const int half = tid >> 7;
    const int ltid = tid & 127;
    const int bid  = 1 + half;
    const int row0 = blockIdx.x * BT + half * HR;

    float* h1 = sm + SM_H1 + half * (UO * HR);
    float* h2 = sm + SM_H2 + half * (UI * HR);
    float* h3 = sm + SM_H3 + half * (UI * HR);
    float* h4 = sm + SM_H4 + half * (UO * HR);
    float* xh = sm + SM_XS + half * (FDIM * HR);

    const int ub = ltid;                 // big GEMMs: u-quad, all 8 rows
    // small GEMMs: lane PAIRS share a u-quad -> smem weight reads dedup to
    // 256B + broadcast (2 crossbar phases instead of 4)
    const int us = ltid >> 1;            // u-quad (0..63)
    const int rs = (ltid & 1) * 4;       // row-quad offset (0 or 4)
    const bool hiq = (ltid & 1);         // which loaded quad rs selects

    // zero state, load dense weights, stage phase-A smem weights
    for (int i = tid; i < UO * HR * 2; i += NTHR) { sm[SM_H1 + i] = 0.f; sm[SM_H4 + i] = 0.f; }
    for (int i = tid; i < UI * HR * 2; i += NTHR) { sm[SM_H2 + i] = 0.f; sm[SM_H3 + i] = 0.f; }
    for (int i = tid; i < UO * FDIM; i += NTHR) wds[i] = g_Wdf[i];
    if (tid < FDIM) bds[tid] = g_bdf[tid];
    if (ltid < HR * FDIM) {
        int r = ltid >> 3, k = ltid & 7;
        xh[k * HR + r] = x[(size_t)(row0 + r) * TDIM * FDIM + k];
    }
    {
        float4* d1 = (float4*)wbig;
        const float4* s1 = (const float4*)g_Wk2f;
        for (int i = tid; i < N_WK2F / 4; i += NTHR) d1[i] = s1[i];
        float4* d2 = (float4*)wsmall;
        const float4* s2 = (const float4*)g_Wr2t;
        for (int i = tid; i < N_WR2T / 4; i += NTHR) d2[i] = s2[i];
    }

    float bb1[4], bb2[4], bb4[4];
#pragma unroll
    for (int g = 0; g < 4; g++) {
        bb1[g] = b1[g * UO + ub];
        bb2[g] = g_b2f[g * UI + us];
        bb4[g] = g_b4f[g * UO + ub];
    }

    float c1v[8], c4v[8], c2v[4], c3v[4];
#pragma unroll
    for (int i = 0; i < 8; i++) { c1v[i] = 0.f; c4v[i] = 0.f; }
#pragma unroll
    for (int i = 0; i < 4; i++) { c2v[i] = 0.f; c3v[i] = 0.f; }

    const float4* Wk1t = (const float4*)g_Wk1t;
    const float4* Wr1t = (const float4*)g_Wr1t;
    const float4* Wr4t = (const float4*)g_Wr4t;
    const float4* Wk3f = (const float4*)g_Wk3f;
    const float4* wbig4   = (const float4*)wbig;
    const float4* wsmall4 = (const float4*)wsmall;

    __syncthreads();

    // ========== Phase A: LSTM1(t) fused with LSTM2(t-1), pipelined ==========
    // Loop-top invariant: h1 = h1(t-1), h2 = h2(t-2), xh = x(t).
    for (int t = 0; t < TDIM; t++) {
        float2 a1[4][4];
        init_acc<4>(a1, bb1);
        float2 a2[4][2];
        init_acc<2>(a2, bb2);

        float4 wA[8], wB[8];

        // stage x weights + block-0 of Wr1t, then consume x (covers block-0 latency)
        {
            float4 xw[FDIM];
#pragma unroll
            for (int k = 0; k < FDIM; k++) xw[k] = __ldg(Wk1t + k * UO + ub);
            LD8(wA, Wr1t, 0);
#pragma unroll
            for (int k = 0; k < FDIM; k++) {
                const float4* xq = (const float4*)(xh + k * HR);
                acc8(a1, xw[k], xq[0], xq[1]);
            }
        }
#pragma unroll 1
        for (int k0 = 0; k0 < 64; k0 += 16) {
            LD8(wB, Wr1t, k0 + 8);
            BODYA_WR(k0, wA);
            LD8(wA, Wr1t, k0 + 16);        // at k0=48 this preloads block 64
            BODYA_WR(k0 + 8, wB);
        }
#pragma unroll 1
        for (int k0 = 64; k0 < 128; k0 += 16) {
            LD8(wB, Wr1t, k0 + 8);
            BODYA_NW(k0, wA);
            LD8(wA, Wr1t, (k0 + 16) & 127);  // wrap keeps address valid
            BODYA_NW(k0 + 8, wB);
        }

        barsync(bid);  // old-state reads complete

        gates_write<4>(a1, c1v, h1 + ub * HR);                  // h1(t)
        if (t > 0) gates_write<2>(a2, c2v, h2 + us * HR + rs);  // h2(t-1)
        if (t + 1 < TDIM && ltid < HR * FDIM) {                 // x(t+1)
            int r = ltid >> 3, k = ltid & 7;
            xh[k * HR + r] = x[(size_t)(row0 + r) * TDIM * FDIM + (t + 1) * FDIM + k];
        }
        barsync(bid);  // new state visible
    }

    // epilogue A: h2(127) from h1(127), h2(126)
    {
        float2 a2[4][2];
        init_acc<2>(a2, bb2);
#pragma unroll 4
        for (int k = 0; k < UI; k++) {
            float4 w2 = wbig4[k * UI + us];
            float4 wr = wsmall4[k * UI + us];
            float4 h1sel = *(const float4*)(h1 + k * HR + rs);
            float4 h2q  = *(const float4*)(h2 + k * HR + rs);
            acc4(a2, w2, h1sel);
            acc4(a2, wr, h2q);
        }
#pragma unroll 4
        for (int k = UI; k < UO; k++) {
            float4 w2 = wbig4[k * UI + us];
            float4 h1sel = *(const float4*)(h1 + k * HR + rs);
            acc4(a2, w2, h1sel);
        }
        barsync(bid);
        gates_write<2>(a2, c2v, h2 + us * HR + rs);  // h2(127)
    }

    // ===== transition: xz3 = enc_bn @ Wk3f + b3f; reload smem for phase B ====
    __syncthreads();   // join halves; h2 final everywhere
    float2 x3[4][2];
    {
        float bb3[4];
#pragma unroll
        for (int g = 0; g < 4; g++) bb3[g] = g_b3f[g * UI + us];
        init_acc<2>(x3, bb3);
#pragma unroll 4
        for (int k = 0; k < UI; k++) {
            float4 w = __ldg(Wk3f + k * UI + us);
            float4 hq = *(const float4*)(h2 + k * HR + rs);
            acc4(x3, w, hq);
        }
    }
    {
        float4* d1 = (float4*)wbig;
        const float4* s1 = (const float4*)g_Wk4f;
        for (int i = tid; i < N_WK4F / 4; i += NTHR) d1[i] = s1[i];
        float4* d2 = (float4*)wsmall;
        const float4* s2 = (const float4*)g_Wr3t;
        for (int i = tid; i < N_WR3T / 4; i += NTHR) d2[i] = s2[i];
    }
    __syncthreads();   // phase-B weights staged

    // ========== Phase B: LSTM3(t) fused with LSTM4(t-1) + Dense(t-2) ========
    // Loop-top invariant: h3 = h3(t-1), h4 = h4(t-2).
    const int dr = ltid >> 3, dc = ltid & 7;
    for (int t = 0; t < TDIM; t++) {
        float2 a3[4][2];
#pragma unroll
        for (int g = 0; g < 4; g++) { a3[g][0] = x3[g][0]; a3[g][1] = x3[g][1]; }
        float2 a4[4][4];
        init_acc<4>(a4, bb4);

        float4 wA[8], wB[8];
        LD8(wA, Wr4t, 0);

        // dense head out(t-2) from h4(t-2) — covers block-0 latency
        if (t >= 2 && ltid < HR * FDIM) {
            float acc = bds[dc];
#pragma unroll 8
            for (int k = 0; k < UO; k++) acc += h4[k * HR + dr] * wds[k * FDIM + dc];
            out[(size_t)(row0 + dr) * TDIM * FDIM + (t - 2) * FDIM + dc] = acc;
        }

#pragma unroll 1
        for (int k0 = 0; k0 < 64; k0 += 16) {
            LD8(wB, Wr4t, k0 + 8);
            BODYB_WR(k0, wA);
            LD8(wA, Wr4t, k0 + 16);        // at k0=48 preloads block 64
            BODYB_WR(k0 + 8, wB);
        }
#pragma unroll 1
        for (int k0 = 64; k0 < 128; k0 += 16) {
            LD8(wB, Wr4t, k0 + 8);
            BODYB_NW(k0, wA);
            LD8(wA, Wr4t, (k0 + 16) & 127);
            BODYB_NW(k0 + 8, wB);
        }

        barsync(bid);  // old-state reads complete

        gates_write<2>(a3, c3v, h3 + us * HR + rs);             // h3(t)
        if (t > 0) gates_write<4>(a4, c4v, h4 + ub * HR);       // h4(t-1)
        barsync(bid);  // new state visible
    }

    // epilogue B: h4(127) from h4(126), h3(127); dense out(126), out(127)
    {
        float2 a4[4][4];
        init_acc<4>(a4, bb4);
#pragma unroll 4
        for (int k = 0; k < UI; k++) {
            float4 w4 = __ldg(Wr4t + k * UO + ub);
            float4 wk = wbig4[k * UO + ub];
            const float4* h4q = (const float4*)(h4 + k * HR);
            const float4* h3q = (const float4*)(h3 + k * HR);
            acc8(a4, w4, h4q[0], h4q[1]);
            acc8(a4, wk, h3q[0], h3q[1]);
        }
#pragma unroll 4
        for (int k = UI; k < UO; k++) {
            float4 w4 = __ldg(Wr4t + k * UO + ub);
            const float4* h4q = (const float4*)(h4 + k * HR);
            acc8(a4, w4, h4q[0], h4q[1]);
        }
        if (ltid < HR * FDIM) {  // out(126) from h4(126)
            float acc = bds[dc];
#pragma unroll 8
            for (int k = 0; k < UO; k++) acc += h4[k * HR + dr] * wds[k * FDIM + dc];
            out[(size_t)(row0 + dr) * TDIM * FDIM + 126 * FDIM + dc] = acc;
        }
        barsync(bid);
        gates_write<4>(a4, c4v, h4 + ub * HR);  // h4(127)
        barsync(bid);
        if (ltid < HR * FDIM) {  // out(127)
            float acc = bds[dc];
#pragma unroll 8
            for (int k = 0; k < UO; k++) acc += h4[k * HR + dr] * wds[k * FDIM + dc];
            out[(size_t)(row0 + dr) * TDIM * FDIM + 127 * FDIM + dc] = acc;
        }
    }
}

// ---------------- launch ------------------------------------------------------
extern "C" void kernel_launch(void* const* d_in, const int* in_sizes, int n_in,
                              void* d_out, int out_size) {
    const float* x   = (const float*)d_in[0];
    const float* Wk1 = (const float*)d_in[1];
    const float* Wr1 = (const float*)d_in[2];
    const float* b1  = (const float*)d_in[3];
    const float* g1  = (const float*)d_in[4];
    const float* be1 = (const float*)d_in[5];
    const float* m1  = (const float*)d_in[6];
    const float* v1  = (const float*)d_in[7];
    const float* Wk2 = (const float*)d_in[8];
    const float* Wr2 = (const float*)d_in[9];
    const float* b2  = (const float*)d_in[10];
    const float* g2  = (const float*)d_in[11];
    const float* be2 = (const float*)d_in[12];
    const float* m2  = (const float*)d_in[13];
    const float* v2  = (const float*)d_in[14];
    const float* Wk3 = (const float*)d_in[15];
    const float* Wr3 = (const float*)d_in[16];
    const float* b3  = (const float*)d_in[17];
    const float* g3  = (const float*)d_in[18];
    const float* be3 = (const float*)d_in[19];
    const float* m3  = (const float*)d_in[20];
    const float* v3  = (const float*)d_in[21];
    const float* Wk4 = (const float*)d_in[22];
    const float* Wr4 = (const float*)d_in[23];
    const float* b4  = (const float*)d_in[24];
    const float* g4  = (const float*)d_in[25];
    const float* be4 = (const float*)d_in[26];
    const float* m4  = (const float*)d_in[27];
    const float* v4  = (const float*)d_in[28];
    const float* Wd  = (const float*)d_in[29];
    const float* bd  = (const float*)d_in[30];

    static bool attr_set = false;
    if (!attr_set) {
        cudaFuncSetAttribute(lstm_ae_kernel,
                             cudaFuncAttributeMaxDynamicSharedMemorySize, SMEM_BYTES);
        attr_set = true;
    }

    prep_all<<<(NTOT + 255) / 256, 256>>>(Wk1, Wr1, Wr2, Wr3, Wr4,
                                          Wk2, b2, Wk3, b3, Wk4, b4, Wd, bd,
                                          g1, be1, m1, v1, g2, be2, m2, v2,
                                          g3, be3, m3, v3, g4, be4, m4, v4);
    lstm_ae_kernel<<<BDIM / BT, NTHR, SMEM_BYTES>>>(x, b1, (float*)d_out);
}

// round 12
// speedup vs baseline: 1.1956x; 1.0804x over previous
#include <cuda_runtime.h>

#define BDIM 2048
#define TDIM 128
#define FDIM 8
#define UO   128
#define UI   64
#define BT   16          // batch rows per CTA (two independent halves of 8)
#define HR   8           // rows per half
#define NTHR 384         // 2 halves x (4 BIG warps + 2 SMALL warps)
#define HALF_T 192
#define BN_EPS 1e-3f

// ---------------- device scratch: BN-folded, gate-contiguous weights ---------
__device__ __align__(16) float g_Wk1t[FDIM * UO * 4];
__device__ __align__(16) float g_Wr1t[UO * UO * 4];
__device__ __align__(16) float g_Wr2t[UI * UI * 4];
__device__ __align__(16) float g_Wr3t[UI * UI * 4];
__device__ __align__(16) float g_Wr4t[UO * UO * 4];
__device__ __align__(16) float g_Wk2f[UO * UI * 4];   // BN1 folded
__device__ __align__(16) float g_Wk3f[UI * UI * 4];   // BN2 folded
__device__ __align__(16) float g_Wk4f[UI * UO * 4];   // BN3 folded
__device__ __align__(16) float g_Wdf[UO * FDIM];      // BN4 folded
__device__ float g_b2f[4 * UI];
__device__ float g_b3f[4 * UI];
__device__ float g_b4f[4 * UO];
__device__ float g_bdf[FDIM];

// ---------------- dynamic smem layout (floats) --------------------------------
#define SM_WBIG   0                            // 32768: Wk2f (A) / Wk4f (B)
#define SM_WSMALL 32768                        // 16384: Wr2t (A) / Wr3t (B)
#define SM_H1     (SM_WSMALL + 16384)          // 2048
#define SM_H2     (SM_H1 + 2048)               // 1024
#define SM_H3     (SM_H2 + 1024)               // 1024
#define SM_H4     (SM_H3 + 1024)               // 2048
#define SM_XS     (SM_H4 + 2048)               // 128
#define SM_WDS    (SM_XS + 128)                // 1024
#define SM_BDS    (SM_WDS + 1024)              // 8
#define SM_TOTAL  (SM_BDS + 8)                 // 56456 floats = 225824 B
#define SMEM_BYTES (SM_TOTAL * 4)

// ---------------- helpers ----------------------------------------------------
__device__ __forceinline__ float2 ffma2f(float2 a, float2 b, float2 c) {
    union U { float2 f; unsigned long long u; };
    U A, B, C, D;
    A.f = a; B.f = b; C.f = c;
    asm("fma.rn.f32x2 %0, %1, %2, %3;" : "=l"(D.u) : "l"(A.u), "l"(B.u), "l"(C.u));
    return D.f;
}

__device__ __forceinline__ void barsync(int id) {
    asm volatile("bar.sync %0, %1;" :: "r"(id), "r"(HALF_T) : "memory");
}

__device__ __forceinline__ float tanh_fast(float x) {
    float y;
    asm("tanh.approx.f32 %0, %1;" : "=f"(y) : "f"(x));
    return y;
}

// sigmoid(x) = 0.5*tanh(0.5x)+0.5 : 1 MUFU instead of 2
__device__ __forceinline__ float sigm(float x) {
    return fmaf(0.5f, tanh_fast(0.5f * x), 0.5f);
}

__device__ __forceinline__ float seluf(float x) {
    const float l = 1.0507009873554805f;
    const float a = 1.6732632423543772f;
    return x > 0.0f ? l * x : l * a * (__expf(x) - 1.0f);
}

__device__ __forceinline__ void gate_update(float zi, float zf, float zg, float zo,
                                            float& c, float& h) {
    float i = sigm(zi), f = sigm(zf), g = seluf(zg), o = sigm(zo);
    c = f * c + i * g;
    h = o * seluf(c);
}

// acc[4][4] covers 8 rows (2 quads); 16 FFMA2
__device__ __forceinline__ void acc8(float2 (&acc)[4][4], float4 w, float4 h0, float4 h1) {
    float ws[4] = {w.x, w.y, w.z, w.w};
#pragma unroll
    for (int g = 0; g < 4; g++) {
        float2 W = make_float2(ws[g], ws[g]);
        acc[g][0] = ffma2f(make_float2(h0.x, h0.y), W, acc[g][0]);
        acc[g][1] = ffma2f(make_float2(h0.z, h0.w), W, acc[g][1]);
        acc[g][2] = ffma2f(make_float2(h1.x, h1.y), W, acc[g][2]);
        acc[g][3] = ffma2f(make_float2(h1.z, h1.w), W, acc[g][3]);
    }
}

__device__ __forceinline__ void init_acc4(float2 (&acc)[4][4], const float b[4]) {
#pragma unroll
    for (int g = 0; g < 4; g++)
#pragma unroll
        for (int p = 0; p < 4; p++) acc[g][p] = make_float2(b[g], b[g]);
}

// gate math + write 8-row h
__device__ __forceinline__ void gates_write8(float2 (&acc)[4][4], float* cvec, float* hrow) {
#pragma unroll
    for (int p = 0; p < 4; p++) {
        {
            float c = cvec[2 * p], h;
            gate_update(acc[0][p].x, acc[1][p].x, acc[2][p].x, acc[3][p].x, c, h);
            cvec[2 * p] = c; hrow[2 * p] = h;
        }
        {
            float c = cvec[2 * p + 1], h;
            gate_update(acc[0][p].y, acc[1][p].y, acc[2][p].y, acc[3][p].y, c, h);
            cvec[2 * p + 1] = c; hrow[2 * p + 1] = h;
        }
    }
}

// ---------------- single merged prep kernel -----------------------------------
#define N_WK1T  (FDIM * UO * 4)
#define N_WR1T  (UO * UO * 4)
#define N_WR2T  (UI * UI * 4)
#define N_WR3T  (UI * UI * 4)
#define N_WR4T  (UO * UO * 4)
#define N_WK2F  (UO * UI * 4)
#define N_WK3F  (UI * UI * 4)
#define N_WK4F  (UI * UO * 4)
#define N_WDF   (UO * FDIM)
#define O1 N_WK1T
#define O2 (O1 + N_WR1T)
#define O3 (O2 + N_WR2T)
#define O4 (O3 + N_WR3T)
#define O5 (O4 + N_WR4T)
#define O6 (O5 + N_WK2F)
#define O7 (O6 + N_WK3F)
#define O8 (O7 + N_WK4F)
#define O9 (O8 + N_WDF)
#define OA (O9 + 4 * UI)
#define OB (OA + 4 * UI)
#define OC (OB + 4 * UO)
#define OD (OC + FDIM)
#define NTOT OD

__device__ __forceinline__ float bn_s(const float* g, const float* v, int k) {
    return g[k] * rsqrtf(v[k] + BN_EPS);
}
__device__ __forceinline__ float bn_sh(const float* g, const float* be, const float* m,
                                       const float* v, int k) {
    float s = g[k] * rsqrtf(v[k] + BN_EPS);
    return be[k] - m[k] * s;
}

__global__ void prep_all(const float* __restrict__ Wk1, const float* __restrict__ Wr1,
                         const float* __restrict__ Wr2, const float* __restrict__ Wr3,
                         const float* __restrict__ Wr4,
                         const float* __restrict__ Wk2, const float* __restrict__ b2,
                         const float* __restrict__ Wk3, const float* __restrict__ b3,
                         const float* __restrict__ Wk4, const float* __restrict__ b4,
                         const float* __restrict__ Wd,  const float* __restrict__ bd,
                         const float* __restrict__ g1, const float* __restrict__ be1,
                         const float* __restrict__ m1, const float* __restrict__ v1,
                         const float* __restrict__ g2, const float* __restrict__ be2,
                         const float* __restrict__ m2, const float* __restrict__ v2,
                         const float* __restrict__ g3, const float* __restrict__ be3,
                         const float* __restrict__ m3, const float* __restrict__ v3,
                         const float* __restrict__ g4, const float* __restrict__ be4,
                         const float* __restrict__ m4, const float* __restrict__ v4) {
    int e = blockIdx.x * blockDim.x + threadIdx.x;
    if (e >= NTOT) return;
    if (e < O1) {
        int g = e & 3, u = (e >> 2) & (UO - 1), k = e >> 9;
        g_Wk1t[e] = Wk1[k * 4 * UO + g * UO + u];
    } else if (e < O2) {
        int i = e - O1;
        int g = i & 3, u = (i >> 2) & (UO - 1), k = i >> 9;
        g_Wr1t[i] = Wr1[k * 4 * UO + g * UO + u];
    } else if (e < O3) {
        int i = e - O2;
        int g = i & 3, u = (i >> 2) & (UI - 1), k = i >> 8;
        g_Wr2t[i] = Wr2[k * 4 * UI + g * UI + u];
    } else if (e < O4) {
        int i = e - O3;
        int g = i & 3, u = (i >> 2) & (UI - 1), k = i >> 8;
        g_Wr3t[i] = Wr3[k * 4 * UI + g * UI + u];
    } else if (e < O5) {
        int i = e - O4;
        int g = i & 3, u = (i >> 2) & (UO - 1), k = i >> 9;
        g_Wr4t[i] = Wr4[k * 4 * UO + g * UO + u];
    } else if (e < O6) {
        int i = e - O5;
        int g = i & 3, u = (i >> 2) & (UI - 1), k = i >> 8;
        g_Wk2f[i] = bn_s(g1, v1, k) * Wk2[k * 4 * UI + g * UI + u];
    } else if (e < O7) {
        int i = e - O6;
        int g = i & 3, u = (i >> 2) & (UI - 1), k = i >> 8;
        g_Wk3f[i] = bn_s(g2, v2, k) * Wk3[k * 4 * UI + g * UI + u];
    } else if (e < O8) {
        int i = e - O7;
        int g = i & 3, u = (i >> 2) & (UO - 1), k = i >> 9;
        g_Wk4f[i] = bn_s(g3, v3, k) * Wk4[k * 4 * UO + g * UO + u];
    } else if (e < O9) {
        int i = e - O8;
        int k = i >> 3;
        g_Wdf[i] = bn_s(g4, v4, k) * Wd[i];
    } else if (e < OA) {
        int c = e - O9;
        float acc = b2[c];
        for (int k = 0; k < UO; k++) acc += bn_sh(g1, be1, m1, v1, k) * Wk2[k * 4 * UI + c];
        g_b2f[c] = acc;
    } else if (e < OB) {
        int c = e - OA;
        float acc = b3[c];
        for (int k = 0; k < UI; k++) acc += bn_sh(g2, be2, m2, v2, k) * Wk3[k * 4 * UI + c];
        g_b3f[c] = acc;
    } else if (e < OC) {
        int c = e - OB;
        float acc = b4[c];
        for (int k = 0; k < UI; k++) acc += bn_sh(g3, be3, m3, v3, k) * Wk4[k * 4 * UO + c];
        g_b4f[c] = acc;
    } else {
        int c = e - OC;
        float acc = bd[c];
        for (int k = 0; k < UO; k++) acc += bn_sh(g4, be4, m4, v4, k) * Wd[k * FDIM + c];
        g_bdf[c] = acc;
    }
}

// 4-deep weight-block load into register buffer (BIG role)
#define LD4(BUF, BASE, K0)                                                  \
    do {                                                                    \
        _Pragma("unroll")                                                   \
        for (int j_ = 0; j_ < 4; j_++)                                      \
            BUF[j_] = __ldg((BASE) + ((K0) + j_) * UO + ub);                \
    } while (0)

// BIG phase-A block: 4 k of Wr1·h1
#define BIGA4(K0, BUF)                                                      \
    do {                                                                    \
        _Pragma("unroll")                                                   \
        for (int j_ = 0; j_ < 4; j_++) {                                    \
            const float4* hq_ = (const float4*)(h1 + ((K0) + j_) * HR);     \
            acc8(a1, BUF[j_], hq_[0], hq_[1]);                              \
        }                                                                   \
    } while (0)

// BIG phase-B block with Wk4f: 4 k of Wr4·h4 + Wk4f·h3
#define BIGB4_WK(K0, BUF)                                                   \
    do {                                                                    \
        _Pragma("unroll")                                                   \
        for (int j_ = 0; j_ < 4; j_++) {                                    \
            int k_ = (K0) + j_;                                             \
            float4 wk_ = wbig4[k_ * UO + ub];                               \
            const float4* h4q_ = (const float4*)(h4 + k_ * HR);             \
            const float4* h3q_ = (const float4*)(h3 + k_ * HR);             \
            acc8(a4, BUF[j_], h4q_[0], h4q_[1]);                            \
            acc8(a4, wk_, h3q_[0], h3q_[1]);                                \
        }                                                                   \
    } while (0)

// BIG phase-B block without Wk4f
#define BIGB4_NW(K0, BUF)                                                   \
    do {                                                                    \
        _Pragma("unroll")                                                   \
        for (int j_ = 0; j_ < 4; j_++) {                                    \
            const float4* h4q_ = (const float4*)(h4 + ((K0) + j_) * HR);    \
            acc8(a4, BUF[j_], h4q_[0], h4q_[1]);                            \
        }                                                                   \
    } while (0)

// ---------------- main: warp-specialized roles, 3 warps/SMSP ------------------
__global__ __launch_bounds__(NTHR, 1)
void lstm_ae_kernel(const float* __restrict__ x,
                    const float* __restrict__ b1,
                    float* __restrict__ out) {
    extern __shared__ __align__(16) float sm[];
    float* wbig   = sm + SM_WBIG;     // Wk2f (phase A) / Wk4f (phase B)
    float* wsmall = sm + SM_WSMALL;   // Wr2t (phase A) / Wr3t (phase B)
    float* wds    = sm + SM_WDS;
    float* bds    = sm + SM_BDS;

    const int tid  = threadIdx.x;
    const int half = (tid >= HALF_T) ? 1 : 0;
    const int ltid = tid - half * HALF_T;
    const int bid  = 1 + half;
    const int row0 = blockIdx.x * BT + half * HR;

    float* h1 = sm + SM_H1 + half * (UO * HR);
    float* h2 = sm + SM_H2 + half * (UI * HR);
    float* h3 = sm + SM_H3 + half * (UI * HR);
    float* h4 = sm + SM_H4 + half * (UO * HR);
    float* xh = sm + SM_XS + half * (FDIM * HR);

    const bool isBig = (ltid < 128);     // warps 0-3 of half: 512-col GEMMs
    const int ub  = ltid;                // BIG: u-quad
    const int sid = ltid - 128;          // SMALL: u-quad (0..63), all 8 rows

    // zero state, load dense weights, stage phase-A smem weights
    for (int i = tid; i < UO * HR * 2; i += NTHR) { sm[SM_H1 + i] = 0.f; sm[SM_H4 + i] = 0.f; }
    for (int i = tid; i < UI * HR * 2; i += NTHR) { sm[SM_H2 + i] = 0.f; sm[SM_H3 + i] = 0.f; }
    for (int i = tid; i < UO * FDIM; i += NTHR) wds[i] = g_Wdf[i];
    if (tid < FDIM) bds[tid] = g_bdf[tid];
    if (ltid < HR * FDIM) {
        int r = ltid >> 3, k = ltid & 7;
        xh[k * HR + r] = x[(size_t)(row0 + r) * TDIM * FDIM + k];
    }
    {
        float4* d1 = (float4*)wbig;
        const float4* s1 = (const float4*)g_Wk2f;
        for (int i = tid; i < N_WK2F / 4; i += NTHR) d1[i] = s1[i];
        float4* d2 = (float4*)wsmall;
        const float4* s2 = (const float4*)g_Wr2t;
        for (int i = tid; i < N_WR2T / 4; i += NTHR) d2[i] = s2[i];
    }

    // persistent per-role state
    float bb1[4], bb2[4], bb4[4];
#pragma unroll
    for (int g = 0; g < 4; g++) {
        bb1[g] = isBig ? b1[g * UO + ub] : 0.f;
        bb2[g] = isBig ? 0.f : g_b2f[g * UI + sid];
        bb4[g] = isBig ? g_b4f[g * UO + ub] : 0.f;
    }
    float cA[8], cB[8];   // BIG: c1/c4 ; SMALL: c2/c3
#pragma unroll
    for (int i = 0; i < 8; i++) { cA[i] = 0.f; cB[i] = 0.f; }

    const float4* Wk1t = (const float4*)g_Wk1t;
    const float4* Wr1t = (const float4*)g_Wr1t;
    const float4* Wr4t = (const float4*)g_Wr4t;
    const float4* Wk3f = (const float4*)g_Wk3f;
    const float4* wbig4   = (const float4*)wbig;
    const float4* wsmall4 = (const float4*)wsmall;

    const int xr = ltid >> 3, xk = ltid & 7;

    __syncthreads();

    // ========== Phase A: BIG = z1(t) ; SMALL = z2(t-1) ======================
    // Loop-top invariant: h1 = h1(t-1), h2 = h2(t-2), xh = x(t).
    for (int t = 0; t < TDIM; t++) {
        float2 a1[4][4];
        if (isBig) {
            init_acc4(a1, bb1);
            float4 wA[4], wB[4];
            // x-part: stage 8 Wk1t loads, prime Wr1 block 0 while consuming x
            LD4(wA, Wk1t, 0);
            LD4(wB, Wk1t, 4);
#pragma unroll
            for (int j = 0; j < 4; j++) {
                const float4* xq = (const float4*)(xh + j * HR);
                acc8(a1, wA[j], xq[0], xq[1]);
            }
            LD4(wA, Wr1t, 0);
#pragma unroll
            for (int j = 0; j < 4; j++) {
                const float4* xq = (const float4*)(xh + (4 + j) * HR);
                acc8(a1, wB[j], xq[0], xq[1]);
            }
            // main k loop: 4-deep ping-pong over Wr1t
#pragma unroll 1
            for (int k0 = 0; k0 < UO; k0 += 8) {
                LD4(wB, Wr1t, k0 + 4);
                BIGA4(k0, wA);
                LD4(wA, Wr1t, (k0 + 8) & 127);
                BIGA4(k0 + 4, wB);
            }
        } else {
            // SMALL: z2(t-1) = Wr2·h2(t-2) + Wk2f·h1(t-1) + b2f
            init_acc4(a1, bb2);
#pragma unroll 8
            for (int k = 0; k < UI; k++) {
                float4 w2 = wbig4[k * UI + sid];
                float4 wr = wsmall4[k * UI + sid];
                const float4* h1q = (const float4*)(h1 + k * HR);
                const float4* h2q = (const float4*)(h2 + k * HR);
                acc8(a1, wr, h2q[0], h2q[1]);
                acc8(a1, w2, h1q[0], h1q[1]);
            }
#pragma unroll 8
            for (int k = UI; k < UO; k++) {
                float4 w2 = wbig4[k * UI + sid];
                const float4* h1q = (const float4*)(h1 + k * HR);
                acc8(a1, w2, h1q[0], h1q[1]);
            }
        }

        barsync(bid);  // old-state reads complete

        if (isBig) {
            gates_write8(a1, cA, h1 + ub * HR);                 // h1(t)
            if (t + 1 < TDIM && ltid < HR * FDIM) {             // x(t+1)
                xh[xk * HR + xr] =
                    x[(size_t)(row0 + xr) * TDIM * FDIM + (t + 1) * FDIM + xk];
            }
        } else if (t > 0) {
            gates_write8(a1, cA, h2 + sid * HR);                // h2(t-1)
        }
        barsync(bid);  // new state visible
    }

    // epilogue A: h2(127) from h1(127), h2(126)  [SMALL only computes]
    {
        float2 a2[4][4];
        if (!isBig) {
            init_acc4(a2, bb2);
#pragma unroll 8
            for (int k = 0; k < UI; k++) {
                float4 w2 = wbig4[k * UI + sid];
                float4 wr = wsmall4[k * UI + sid];
                const float4* h1q = (const float4*)(h1 + k * HR);
                const float4* h2q = (const float4*)(h2 + k * HR);
                acc8(a2, wr, h2q[0], h2q[1]);
                acc8(a2, w2, h1q[0], h1q[1]);
            }
#pragma unroll 8
            for (int k = UI; k < UO; k++) {
                float4 w2 = wbig4[k * UI + sid];
                const float4* h1q = (const float4*)(h1 + k * HR);
                acc8(a2, w2, h1q[0], h1q[1]);
            }
        }
        barsync(bid);
        if (!isBig) gates_write8(a2, cA, h2 + sid * HR);  // h2(127)
    }

    // ===== transition: x3 = enc_bn @ Wk3f + b3f (SMALL); restage weights =====
    __syncthreads();   // h2(127) visible CTA-wide
    float2 x3[4][4];
    if (!isBig) {
        float bb3[4];
#pragma unroll
        for (int g = 0; g < 4; g++) bb3[g] = g_b3f[g * UI + sid];
        init_acc4(x3, bb3);
#pragma unroll 8
        for (int k = 0; k < UI; k++) {
            float4 w = __ldg(Wk3f + k * UI + sid);
            const float4* hq = (const float4*)(h2 + k * HR);
            acc8(x3, w, hq[0], hq[1]);
        }
    }
    __syncthreads();   // all x3 reads done before restage
    {
        float4* d1 = (float4*)wbig;
        const float4* s1 = (const float4*)g_Wk4f;
        for (int i = tid; i < N_WK4F / 4; i += NTHR) d1[i] = s1[i];
        float4* d2 = (float4*)wsmall;
        const float4* s2 = (const float4*)g_Wr3t;
        for (int i = tid; i < N_WR3T / 4; i += NTHR) d2[i] = s2[i];
    }
    __syncthreads();   // phase-B weights staged

#pragma unroll
    for (int i = 0; i < 8; i++) { cA[i] = 0.f; cB[i] = 0.f; }

    // ========== Phase B: BIG = z4(t-1) ; SMALL = z3(t) + Dense(t-2) =========
    // Loop-top invariant: h3 = h3(t-1), h4 = h4(t-2).
    const int dr = sid >> 3, dc = sid & 7;   // SMALL: 64 threads = 8x8 dense map
    for (int t = 0; t < TDIM; t++) {
        float2 a4[4][4];
        if (isBig) {
            init_acc4(a4, bb4);
            float4 wA[4], wB[4];
            LD4(wA, Wr4t, 0);
#pragma unroll 1
            for (int k0 = 0; k0 < UI; k0 += 8) {
                LD4(wB, Wr4t, k0 + 4);
                BIGB4_WK(k0, wA);
                LD4(wA, Wr4t, k0 + 8);
                BIGB4_WK(k0 + 4, wB);
            }
#pragma unroll 1
            for (int k0 = UI; k0 < UO; k0 += 8) {
                LD4(wB, Wr4t, k0 + 4);
                BIGB4_NW(k0, wA);
                LD4(wA, Wr4t, (k0 + 8) & 127);
                BIGB4_NW(k0 + 4, wB);
            }
        } else {
            // SMALL: dense head out(t-2) from h4(t-2)
            if (t >= 2) {
                float acc = bds[dc];
#pragma unroll 8
                for (int k = 0; k < UO; k++) acc += h4[k * HR + dr] * wds[k * FDIM + dc];
                out[(size_t)(row0 + dr) * TDIM * FDIM + (t - 2) * FDIM + dc] = acc;
            }
            // z3(t) = x3 + Wr3·h3(t-1)
#pragma unroll
            for (int g = 0; g < 4; g++)
#pragma unroll
                for (int p = 0; p < 4; p++) a4[g][p] = x3[g][p];
#pragma unroll 8
            for (int k = 0; k < UI; k++) {
                float4 w3 = wsmall4[k * UI + sid];
                const float4* h3q = (const float4*)(h3 + k * HR);
                acc8(a4, w3, h3q[0], h3q[1]);
            }
        }

        barsync(bid);  // old-state reads complete

        if (isBig) {
            if (t > 0) gates_write8(a4, cB, h4 + ub * HR);      // h4(t-1)
        } else {
            gates_write8(a4, cB, h3 + sid * HR);                // h3(t)
        }
        barsync(bid);  // new state visible
    }

    // epilogue B: h4(127) [BIG]; dense out(126), out(127) [SMALL]
    {
        float2 a4[4][4];
        if (isBig) {
            init_acc4(a4, bb4);
#pragma unroll 4
            for (int k = 0; k < UI; k++) {
                float4 w4 = __ldg(Wr4t + k * UO + ub);
                float4 wk = wbig4[k * UO + ub];
                const float4* h4q = (const float4*)(h4 + k * HR);
                const float4* h3q = (const float4*)(h3 + k * HR);
                acc8(a4, w4, h4q[0], h4q[1]);
                acc8(a4, wk, h3q[0], h3q[1]);
            }
#pragma unroll 4
            for (int k = UI; k < UO; k++) {
                float4 w4 = __ldg(Wr4t + k * UO + ub);
                const float4* h4q = (const float4*)(h4 + k * HR);
                acc8(a4, w4, h4q[0], h4q[1]);
            }
        } else {  // out(126) from h4(126)
            float acc = bds[dc];
#pragma unroll 8
            for (int k = 0; k < UO; k++) acc += h4[k * HR + dr] * wds[k * FDIM + dc];
            out[(size_t)(row0 + dr) * TDIM * FDIM + 126 * FDIM + dc] = acc;
        }
        barsync(bid);
        if (isBig) gates_write8(a4, cB, h4 + ub * HR);  // h4(127)
        barsync(bid);
        if (!isBig) {  // out(127)
            float acc = bds[dc];
#pragma unroll 8
            for (int k = 0; k < UO; k++) acc += h4[k * HR + dr] * wds[k * FDIM + dc];
            out[(size_t)(row0 + dr) * TDIM * FDIM + 127 * FDIM + dc] = acc;
        }
    }
}

// ---------------- launch ------------------------------------------------------
extern "C" void kernel_launch(void* const* d_in, const int* in_sizes, int n_in,
                              void* d_out, int out_size) {
    const float* x   = (const float*)d_in[0];
    const float* Wk1 = (const float*)d_in[1];
    const float* Wr1 = (const float*)d_in[2];
    const float* b1  = (const float*)d_in[3];
    const float* g1  = (const float*)d_in[4];
    const float* be1 = (const float*)d_in[5];
    const float* m1  = (const float*)d_in[6];
    const float* v1  = (const float*)d_in[7];
    const float* Wk2 = (const float*)d_in[8];
    const float* Wr2 = (const float*)d_in[9];
    const float* b2  = (const float*)d_in[10];
    const float* g2  = (const float*)d_in[11];
    const float* be2 = (const float*)d_in[12];
    const float* m2  = (const float*)d_in[13];
    const float* v2  = (const float*)d_in[14];
    const float* Wk3 = (const float*)d_in[15];
    const float* Wr3 = (const float*)d_in[16];
    const float* b3  = (const float*)d_in[17];
    const float* g3  = (const float*)d_in[18];
    const float* be3 = (const float*)d_in[19];
    const float* m3  = (const float*)d_in[20];
    const float* v3  = (const float*)d_in[21];
    const float* Wk4 = (const float*)d_in[22];
    const float* Wr4 = (const float*)d_in[23];
    const float* b4  = (const float*)d_in[24];
    const float* g4  = (const float*)d_in[25];
    const float* be4 = (const float*)d_in[26];
    const float* m4  = (const float*)d_in[27];
    const float* v4  = (const float*)d_in[28];
    const float* Wd  = (const float*)d_in[29];
    const float* bd  = (const float*)d_in[30];

    static bool attr_set = false;
    if (!attr_set) {
        cudaFuncSetAttribute(lstm_ae_kernel,
                             cudaFuncAttributeMaxDynamicSharedMemorySize, SMEM_BYTES);
        attr_set = true;
    }

    prep_all<<<(NTOT + 255) / 256, 256>>>(Wk1, Wr1, Wr2, Wr3, Wr4,
                                          Wk2, b2, Wk3, b3, Wk4, b4, Wd, bd,
                                          g1, be1, m1, v1, g2, be2, m2, v2,
                                          g3, be3, m3, v3, g4, be4, m4, v4);
    lstm_ae_kernel<<<BDIM / BT, NTHR, SMEM_BYTES>>>(x, b1, (float*)d_out);
}